// round 7
// baseline (speedup 1.0000x reference)
#include <cuda_runtime.h>

// Problem constants
#define B_    256
#define T_    2048
#define F_    64
#define H_    512
#define C_    128

// Partitioning: 32 j-chunks (16 h-units each) x 4 batch-chunks (64 batches) = 128 CTAs
#define NJ    32
#define NCTA  128
#define NTHR  256
#define JT    16      // h-units per CTA (=> 64 gate rows)
#define BT    64      // batches per CTA

// SMEM strides (padded; keep 16B alignment for float4)
#define WS_STR  72
#define PAN_STR 72
#define HN_STR  68

// ---------------- device globals (static scratch; zero-initialized at load) --
__device__ float g_hT[2][H_][B_];            // transposed h state, double buffered (1 MB)
__device__ float g_part[2][NJ][B_][C_];      // decoder partial logits, parity buffered (8 MB)
__device__ unsigned int g_count = 0;
__device__ volatile unsigned int g_sense = 0;

__device__ __forceinline__ float sigm(float x) { return 1.0f / (1.0f + expf(-x)); }

// SMEM layout (floats)
#define OFF_WS    0
#define OFF_PAN   (OFF_WS   + 576 * WS_STR)          // 41472
#define OFF_HN    (OFF_PAN  + 64 * PAN_STR)          // 46080
#define OFF_WD    (OFF_HN   + JT * HN_STR)           // 47168
#define OFF_BSUM  (OFF_WD   + JT * C_)               // 49216
#define OFF_BD    (OFF_BSUM + 64)                    // 49280
#define OFF_RED   (OFF_BD   + C_)                    // 49408
#define SMEM_FLOATS (OFF_RED + 16)                   // 49424
#define SMEM_BYTES  (SMEM_FLOATS * 4)                // 197,696 B

__global__ void __launch_bounds__(NTHR, 1) lstm_persist_kernel(
    const float* __restrict__ X,    // [B, T, F]
    const float* __restrict__ Wih,  // [4H, F]
    const float* __restrict__ Whh,  // [4H, H]
    const float* __restrict__ bih,  // [4H]
    const float* __restrict__ bhh,  // [4H]
    const float* __restrict__ Wd,   // [C, H]
    const float* __restrict__ bd,   // [C]
    float* __restrict__ out)        // [B, T*C]
{
    extern __shared__ float sm[];
    float* ws   = sm + OFF_WS;    // [576][WS_STR]  row r = jj*4 + gate
    float* pan  = sm + OFF_PAN;   // [64][PAN_STR]  activation panel [k][b]
    float* hn   = sm + OFF_HN;    // [16][HN_STR]   h_new staging [jj][b]
    float* wd   = sm + OFF_WD;    // [16][128]      W_d slice [jj][c]
    float* bsum = sm + OFF_BSUM;  // [64]
    float* bds  = sm + OFF_BD;    // [128]
    float* red  = sm + OFF_RED;   // [16]           softmax cross-warp reduce

    const int tid = threadIdx.x;
    const int cta = blockIdx.x;
    const int jb  = cta & 31;         // h-chunk id
    const int bb  = cta >> 5;         // batch-chunk id
    const int J0  = jb * JT;
    const int b0  = bb * BT;
    const int tx  = tid & 15;         // jj index (4 gate rows)
    const int ty  = tid >> 4;         // batch quad index

    // ---- one-time SMEM init: weights + biases (stationary for whole launch) ----
    for (int idx = tid; idx < 576 * 64; idx += NTHR) {
        int k = idx >> 6, r = idx & 63;
        int jj = r >> 2, g = r & 3;
        int grow = g * H_ + J0 + jj;             // PyTorch gate order i,f,g,o
        float v = (k < F_) ? Wih[(size_t)grow * F_ + k]
                           : Whh[(size_t)grow * H_ + (k - F_)];
        ws[k * WS_STR + r] = v;
    }
    for (int idx = tid; idx < JT * C_; idx += NTHR) {
        int jj = idx >> 7, c = idx & 127;
        wd[jj * C_ + c] = Wd[(size_t)c * H_ + J0 + jj];
    }
    if (tid < 64) {
        int jj = tid >> 2, g = tid & 3;
        bsum[tid] = bih[g * H_ + J0 + jj] + bhh[g * H_ + J0 + jj];
    }
    if (tid < C_) bds[tid] = bd[tid];

    float creg[4] = {0.f, 0.f, 0.f, 0.f};   // cell state: jj=tx, 4 batches (ty*4+q)
    __syncthreads();

    for (int t = 0; t < T_; ++t) {
        const int par = t & 1;

        float acc[4][4];
        #pragma unroll
        for (int i = 0; i < 4; ++i)
            #pragma unroll
            for (int j = 0; j < 4; ++j) acc[i][j] = 0.f;

        // ---- gates GEMM: 9 K-panels of 64 (panel 0 = x, 1..8 = h) ----
        for (int p = 0; p < 9; ++p) {
            if (p == 0) {
                // stage x[b, t, 0:64] transposed into pan[k][b]
                int b_l = tid >> 2, q = tid & 3;
                const float* xp = X + ((size_t)(b0 + b_l) * T_ + t) * F_;
                #pragma unroll
                for (int it = 0; it < 4; ++it) {
                    int k0 = q * 16 + it * 4;
                    float4 v = *(const float4*)(xp + k0);
                    pan[(k0 + 0) * PAN_STR + b_l] = v.x;
                    pan[(k0 + 1) * PAN_STR + b_l] = v.y;
                    pan[(k0 + 2) * PAN_STR + b_l] = v.z;
                    pan[(k0 + 3) * PAN_STR + b_l] = v.w;
                }
            } else {
                // stage hT[par][hj][b0..b0+63] -> pan[kk][col] (already transposed)
                int kk = tid >> 2, q = tid & 3;
                const float* hp = &g_hT[par][(p - 1) * 64 + kk][b0];
                #pragma unroll
                for (int it = 0; it < 4; ++it) {
                    int col = q * 16 + it * 4;
                    float4 v = __ldcg((const float4*)(hp + col)); // bypass stale L1
                    *(float4*)(pan + kk * PAN_STR + col) = v;
                }
            }
            __syncthreads();

            const float* wrow = ws + p * 64 * WS_STR + tx * 4;
            const float* prow = pan + ty * 4;
            #pragma unroll 8
            for (int kk = 0; kk < 64; ++kk) {
                float4 wv = *(const float4*)(wrow + kk * WS_STR);
                float4 hv = *(const float4*)(prow + kk * PAN_STR);
                acc[0][0] += wv.x * hv.x; acc[0][1] += wv.x * hv.y;
                acc[0][2] += wv.x * hv.z; acc[0][3] += wv.x * hv.w;
                acc[1][0] += wv.y * hv.x; acc[1][1] += wv.y * hv.y;
                acc[1][2] += wv.y * hv.z; acc[1][3] += wv.y * hv.w;
                acc[2][0] += wv.z * hv.x; acc[2][1] += wv.z * hv.y;
                acc[2][2] += wv.z * hv.z; acc[2][3] += wv.z * hv.w;
                acc[3][0] += wv.w * hv.x; acc[3][1] += wv.w * hv.y;
                acc[3][2] += wv.w * hv.z; acc[3][3] += wv.w * hv.w;
            }
            __syncthreads();
        }

        // ---- cell update (c stays in registers) ----
        #pragma unroll
        for (int bq = 0; bq < 4; ++bq) {
            float pi = acc[0][bq] + bsum[tx * 4 + 0];
            float pf = acc[1][bq] + bsum[tx * 4 + 1];
            float pg = acc[2][bq] + bsum[tx * 4 + 2];
            float po = acc[3][bq] + bsum[tx * 4 + 3];
            float iv = sigm(pi), fv = sigm(pf), gv = tanhf(pg), ov = sigm(po);
            float cn = fv * creg[bq] + iv * gv;
            creg[bq] = cn;
            hn[tx * HN_STR + ty * 4 + bq] = ov * tanhf(cn);
        }
        __syncthreads();

        // ---- write h_new to global (next parity buffer), coalesced ----
        {
            int row = tid >> 4, cq = tid & 15;
            float4 v = *(const float4*)(hn + row * HN_STR + cq * 4);
            *(float4*)(&g_hT[par ^ 1][J0 + row][b0 + cq * 4]) = v;
        }

        // ---- decoder partial logits from LOCAL h_new slice (relu fused) ----
        {
            int cq = tid >> 6, b_l = tid & 63;
            float accd[32];
            #pragma unroll
            for (int i = 0; i < 32; ++i) accd[i] = 0.f;
            #pragma unroll
            for (int kk = 0; kk < JT; ++kk) {
                float hv = fmaxf(hn[kk * HN_STR + b_l], 0.f);
                const float4* wp = (const float4*)(wd + kk * C_ + cq * 32);
                #pragma unroll
                for (int j = 0; j < 8; ++j) {
                    float4 w = wp[j];
                    accd[4 * j + 0] += w.x * hv; accd[4 * j + 1] += w.y * hv;
                    accd[4 * j + 2] += w.z * hv; accd[4 * j + 3] += w.w * hv;
                }
            }
            float4* dst = (float4*)(&g_part[par][jb][b0 + b_l][cq * 32]);
            #pragma unroll
            for (int j = 0; j < 8; ++j)
                dst[j] = make_float4(accd[4 * j + 0], accd[4 * j + 1],
                                     accd[4 * j + 2], accd[4 * j + 3]);
        }

        // ---- grid-wide sync (sense-reversing; 2048/launch -> state resets) ----
        {
            unsigned target = (unsigned)((t & 1) ^ 1);
            __syncthreads();
            if (tid == 0) {
                __threadfence();                      // publish hT + partials to L2
                unsigned v = atomicAdd(&g_count, 1u);
                if (v == NCTA - 1) {
                    g_count = 0;
                    __threadfence();
                    g_sense = target;
                } else {
                    while (g_sense != target) { __nanosleep(64); }
                }
                __threadfence();
            }
            __syncthreads();
        }

        // ---- phase 4: reduce partials + softmax + write out (2 batches/CTA) ----
        {
            int half = tid >> 7;            // 0..1
            int c    = tid & 127;
            int b    = cta * 2 + half;
            float v = bds[c];
            #pragma unroll
            for (int j2 = 0; j2 < NJ; ++j2)
                v += __ldcg(&g_part[par][j2][b][c]);
            int lane = tid & 31, wid = tid >> 5;
            float m = v;
            #pragma unroll
            for (int o = 16; o; o >>= 1)
                m = fmaxf(m, __shfl_xor_sync(0xffffffffu, m, o));
            if (lane == 0) red[wid] = m;
            __syncthreads();
            float gm = fmaxf(fmaxf(red[half * 4 + 0], red[half * 4 + 1]),
                             fmaxf(red[half * 4 + 2], red[half * 4 + 3]));
            float e = expf(v - gm);
            float s = e;
            #pragma unroll
            for (int o = 16; o; o >>= 1)
                s += __shfl_xor_sync(0xffffffffu, s, o);
            if (lane == 0) red[8 + wid] = s;
            __syncthreads();
            float gs = red[8 + half * 4 + 0] + red[8 + half * 4 + 1] +
                       red[8 + half * 4 + 2] + red[8 + half * 4 + 3];
            out[(size_t)b * (T_ * C_) + (size_t)t * C_ + c] = e / gs;
        }
        __syncthreads();
    }

    // ---- restore g_hT[0] to zeros so every launch/replay is identical ----
    {
        int row = tid >> 4, cq = tid & 15;
        *(float4*)(&g_hT[0][J0 + row][b0 + cq * 4]) = make_float4(0.f, 0.f, 0.f, 0.f);
    }
}

extern "C" void kernel_launch(void* const* d_in, const int* in_sizes, int n_in,
                              void* d_out, int out_size) {
    (void)in_sizes; (void)n_in; (void)out_size;
    const float* x   = (const float*)d_in[0];
    const float* Wih = (const float*)d_in[1];
    const float* Whh = (const float*)d_in[2];
    const float* bih = (const float*)d_in[3];
    const float* bhh = (const float*)d_in[4];
    const float* Wd  = (const float*)d_in[5];
    const float* bd  = (const float*)d_in[6];
    float* out = (float*)d_out;

    cudaFuncSetAttribute(lstm_persist_kernel,
                         cudaFuncAttributeMaxDynamicSharedMemorySize, SMEM_BYTES);
    lstm_persist_kernel<<<NCTA, NTHR, SMEM_BYTES>>>(x, Wih, Whh, bih, bhh, Wd, bd, out);
}